// round 8
// baseline (speedup 1.0000x reference)
#include <cuda_runtime.h>

// VariableAnnuity: per-path PnL over 60 monthly steps.
//
// R6 changes:
//  * GP 320 -> 192 (grid error still ~1000x under the 1e-3 gate; lerp is
//    exact off kink cells, kink error ~ h). 180 blocks keeps all SMs busy.
//  * Table layer-2 uses packed fma.rn.f32x2 (FFMA2): adjacent j's pair into
//    64-bit accumulators; W2 read as double2 so .x/.y are ready f32x2
//    operands (no weight packs). Per-k issues: 72 -> 42, FMA instrs halved.
//  * Path kernel: 4 -> 6 step-chunks per path (12288 warps) to hide the
//    dependent table-load chain.

#define NSTEP  60
#define HID    128
#define NBATCH 65536
#define GP     192                    // grid points (3 blocks x 64 per step)
#define S_HI   16.0f                  // max reachable spot ~11.6
#define H_S    (S_HI / 191.0f)
#define INV_HS (191.0f / S_HI)

__device__ float  g_table[NSTEP * GP];   // net(s_g, t_i)
__device__ float4 g_stepc[NSTEP];        // {delta_mult, fee_c, pay_c1, pay_c2}

typedef unsigned long long u64;

static __device__ __forceinline__ u64 pack2(float lo, float hi) {
    u64 r;
    asm("mov.b64 %0, {%1, %2};" : "=l"(r) : "r"(__float_as_uint(lo)), "r"(__float_as_uint(hi)));
    return r;
}
static __device__ __forceinline__ u64 fma2(u64 a, u64 b, u64 c) {
    u64 d;
    asm("fma.rn.f32x2 %0, %1, %2, %3;" : "=l"(d) : "l"(a), "l"(b), "l"(c));
    return d;
}
static __device__ __forceinline__ void unpack2(u64 v, float& lo, float& hi) {
    unsigned a, b;
    asm("mov.b64 {%0, %1}, %2;" : "=r"(a), "=r"(b) : "l"(v));
    lo = __uint_as_float(a); hi = __uint_as_float(b);
}

// ---------------------------------------------------------------------------
// Phase 1: tabulate net on 60 steps x 192 linear-spot grid points.
// Block = 128 threads: jc = tid>>5 (32 j's), gl = tid&31; thread handles
// grid points gl and gl+32. Layer 2 in packed f32x2.
// grid = 60 steps * 3 g-blocks = 180 blocks.
// ---------------------------------------------------------------------------
__global__ __launch_bounds__(128)
void va_table_kernel(const float* __restrict__ W1, const float* __restrict__ b1,
                     const float* __restrict__ W2, const float* __restrict__ b2,
                     const float* __restrict__ W3, const float* __restrict__ b3)
{
    __shared__ float h1s[64][129];     // pad 129 -> conflict-free reads
    __shared__ float part[4][64];

    int step = blockIdx.x / 3;
    int gb   = blockIdx.x - step * 3;
    int tid  = threadIdx.x;
    int jc   = tid >> 5;               // 0..3  j-chunk (one warp each)
    int gl   = tid & 31;               // 0..31 grid-point slot
    float tval = (float)step * (1.0f / 12.0f);

    // side job: block 0 fills the per-step constant table
    if (blockIdx.x == 0 && tid < NSTEP) {
        float ti   = (float)tid * (1.0f / 12.0f);
        float elam = expf(-0.01f * ti);
        float efee = expf(-0.0196f * ti);
        float dm   = (1.0f - expf(-0.01f * (5.0f - ti))) * 100.0f;
        float fc   = 0.0196f * (1.0f / 12.0f) * 100.0f * efee * elam;
        float pc1  = 0.01f   * (1.0f / 12.0f) * 100.0f * elam;
        float pc2  = 0.01f   * (1.0f / 12.0f) * 100.0f * efee * elam;
        g_stepc[tid] = make_float4(dm, fc, pc1, pc2);
    }

    // h1 for this block's 64 grid points; thread fills 32 k's for 2 g's
    {
        float s0 = (float)(gb * 64 + gl)      * H_S;
        float s1 = (float)(gb * 64 + gl + 32) * H_S;
        int   k0 = jc * 32;
#pragma unroll
        for (int k = 0; k < 32; ++k) {
            int kk = k0 + k;
            float wa = __ldg(W1 + kk);
            float wb = fmaf(tval, __ldg(W1 + HID + kk), __ldg(b1 + kk));
            h1s[gl     ][kk] = fmaxf(fmaf(s0, wa, wb), 0.0f);
            h1s[gl + 32][kk] = fmaxf(fmaf(s1, wa, wb), 0.0f);
        }
    }
    __syncthreads();

    // layer 2: 32 j-outputs (16 f32x2 pairs) for each of 2 grid points
    int j0 = jc * 32;
    u64 acc0[16], acc1[16];
#pragma unroll
    for (int q = 0; q < 8; ++q) {
        double2 b = __ldg((const double2*)(b2 + j0) + q);
        acc0[2*q  ] = acc1[2*q  ] = __double_as_longlong(b.x);
        acc0[2*q+1] = acc1[2*q+1] = __double_as_longlong(b.y);
    }
#pragma unroll 4
    for (int k = 0; k < HID; ++k) {
        u64 ha2 = pack2(h1s[gl     ][k], h1s[gl     ][k]);
        u64 hb2 = pack2(h1s[gl + 32][k], h1s[gl + 32][k]);
        const double2* wrow = (const double2*)(W2 + k * HID + j0);
#pragma unroll
        for (int q = 0; q < 8; ++q) {
            double2 w = __ldg(wrow + q);          // 4 floats = 2 f32x2 operands
            u64 w0 = __double_as_longlong(w.x);
            u64 w1 = __double_as_longlong(w.y);
            acc0[2*q  ] = fma2(ha2, w0, acc0[2*q  ]);
            acc0[2*q+1] = fma2(ha2, w1, acc0[2*q+1]);
            acc1[2*q  ] = fma2(hb2, w0, acc1[2*q  ]);
            acc1[2*q+1] = fma2(hb2, w1, acc1[2*q+1]);
        }
    }

    // layer 3 partial dot (unpack, relu, dot with W3)
    float oa = 0.0f, ob = 0.0f;
#pragma unroll
    for (int q = 0; q < 16; ++q) {
        float2 w3 = __ldg((const float2*)(W3 + j0) + q);
        float x0, x1, y0, y1;
        unpack2(acc0[q], x0, x1);
        unpack2(acc1[q], y0, y1);
        oa = fmaf(fmaxf(x0, 0.0f), w3.x, oa);
        oa = fmaf(fmaxf(x1, 0.0f), w3.y, oa);
        ob = fmaf(fmaxf(y0, 0.0f), w3.x, ob);
        ob = fmaf(fmaxf(y1, 0.0f), w3.y, ob);
    }
    part[jc][gl]      = oa;
    part[jc][gl + 32] = ob;
    __syncthreads();

    if (tid < 64) {
        float o = __ldg(b3) + part[0][tid] + part[1][tid] + part[2][tid] + part[3][tid];
        g_table[step * GP + gb * 64 + tid] = o;
    }
}

// ---------------------------------------------------------------------------
// Phase 2: per-path PnL. Steps are independent terms -> 6 chunks of 10 per
// path (12288 warps), smem reduce. Block = 64 paths x 6 chunks.
// ---------------------------------------------------------------------------
__global__ __launch_bounds__(384)
void va_path_kernel(const float* __restrict__ spots, float* __restrict__ out)
{
    __shared__ float red[6][64];

    int tid   = threadIdx.x;
    int chunk = tid >> 6;              // 0..5
    int pl    = tid & 63;
    int p     = blockIdx.x * 64 + pl;
    int i0    = chunk * 10;

    float pnl = 0.0f;
    float s = __ldg(spots + i0 * NBATCH + p);

#pragma unroll
    for (int k = 0; k < 10; ++k) {
        int i = i0 + k;
        float s_next = __ldg(spots + (i + 1) * NBATCH + p);
        float4 c = __ldg(&g_stepc[i]);

        // exact-PWL lerp on linear spot grid (s >= 0 always; clamp high only)
        float u = fminf(s * INV_HS, 190.999f);
        int   ig = (int)u;
        float f  = u - (float)ig;
        const float* row = g_table + i * GP + ig;
        float o0 = __ldg(row);
        float o1 = __ldg(row + 1);
        float netv = fmaf(o1 - o0, f, o0);

        // delta = -(net^2) * dm   (min(exp(-0.01*delta),1) == 1 exactly)
        float delta = -(netv * netv) * c.x;
        // inc_pnl = fee - payout = fc*s - max(pc1 - pc2*s, 0)
        float inc = fmaf(c.y, s, -fmaxf(fmaf(-c.w, s, c.z), 0.0f));

        pnl = pnl + inc + delta * (s_next - s);
        s = s_next;
    }

    red[chunk][pl] = pnl;
    __syncthreads();

    if (tid < 64) {
        out[blockIdx.x * 64 + tid] =
            ((red[0][tid] + red[1][tid]) + (red[2][tid] + red[3][tid]))
            + (red[4][tid] + red[5][tid]);
    }
}

// ---------------------------------------------------------------------------
extern "C" void kernel_launch(void* const* d_in, const int* in_sizes, int n_in,
                              void* d_out, int out_size)
{
    const float* spots = (const float*)d_in[0];   // [61, 65536]
    const float* W1    = (const float*)d_in[1];   // [2, 128]
    const float* b1    = (const float*)d_in[2];   // [128]
    const float* W2    = (const float*)d_in[3];   // [128, 128]
    const float* b2    = (const float*)d_in[4];   // [128]
    const float* W3    = (const float*)d_in[5];   // [128, 1]
    const float* b3    = (const float*)d_in[6];   // [1]

    va_table_kernel<<<NSTEP * 3, 128>>>(W1, b1, W2, b2, W3, b3);
    va_path_kernel<<<NBATCH / 64, 384>>>(spots, (float*)d_out);
}

// round 9
// speedup vs baseline: 1.0039x; 1.0039x over previous
#include <cuda_runtime.h>

// VariableAnnuity: per-path PnL over 60 monthly steps.
//
// R6 changes:
//  * GP 320 -> 192 (grid error still ~1000x under the 1e-3 gate; lerp is
//    exact off kink cells, kink error ~ h). 180 blocks keeps all SMs busy.
//  * Table layer-2 uses packed fma.rn.f32x2 (FFMA2): adjacent j's pair into
//    64-bit accumulators; W2 read as double2 so .x/.y are ready f32x2
//    operands (no weight packs). Per-k issues: 72 -> 42, FMA instrs halved.
//  * Path kernel: 4 -> 6 step-chunks per path (12288 warps) to hide the
//    dependent table-load chain.

#define NSTEP  60
#define HID    128
#define NBATCH 65536
#define GP     192                    // grid points (3 blocks x 64 per step)
#define S_HI   16.0f                  // max reachable spot ~11.6
#define H_S    (S_HI / 191.0f)
#define INV_HS (191.0f / S_HI)

__device__ float  g_table[NSTEP * GP];   // net(s_g, t_i)
__device__ float4 g_stepc[NSTEP];        // {delta_mult, fee_c, pay_c1, pay_c2}

typedef unsigned long long u64;

static __device__ __forceinline__ u64 pack2(float lo, float hi) {
    u64 r;
    asm("mov.b64 %0, {%1, %2};" : "=l"(r) : "r"(__float_as_uint(lo)), "r"(__float_as_uint(hi)));
    return r;
}
static __device__ __forceinline__ u64 fma2(u64 a, u64 b, u64 c) {
    u64 d;
    asm("fma.rn.f32x2 %0, %1, %2, %3;" : "=l"(d) : "l"(a), "l"(b), "l"(c));
    return d;
}
static __device__ __forceinline__ void unpack2(u64 v, float& lo, float& hi) {
    unsigned a, b;
    asm("mov.b64 {%0, %1}, %2;" : "=r"(a), "=r"(b) : "l"(v));
    lo = __uint_as_float(a); hi = __uint_as_float(b);
}

// ---------------------------------------------------------------------------
// Phase 1: tabulate net on 60 steps x 192 linear-spot grid points.
// Block = 128 threads: jc = tid>>5 (32 j's), gl = tid&31; thread handles
// grid points gl and gl+32. Layer 2 in packed f32x2.
// grid = 60 steps * 3 g-blocks = 180 blocks.
// ---------------------------------------------------------------------------
__global__ __launch_bounds__(128)
void va_table_kernel(const float* __restrict__ W1, const float* __restrict__ b1,
                     const float* __restrict__ W2, const float* __restrict__ b2,
                     const float* __restrict__ W3, const float* __restrict__ b3)
{
    __shared__ float h1s[64][129];     // pad 129 -> conflict-free reads
    __shared__ float part[4][64];

    int step = blockIdx.x / 3;
    int gb   = blockIdx.x - step * 3;
    int tid  = threadIdx.x;
    int jc   = tid >> 5;               // 0..3  j-chunk (one warp each)
    int gl   = tid & 31;               // 0..31 grid-point slot
    float tval = (float)step * (1.0f / 12.0f);

    // side job: block 0 fills the per-step constant table
    if (blockIdx.x == 0 && tid < NSTEP) {
        float ti   = (float)tid * (1.0f / 12.0f);
        float elam = expf(-0.01f * ti);
        float efee = expf(-0.0196f * ti);
        float dm   = (1.0f - expf(-0.01f * (5.0f - ti))) * 100.0f;
        float fc   = 0.0196f * (1.0f / 12.0f) * 100.0f * efee * elam;
        float pc1  = 0.01f   * (1.0f / 12.0f) * 100.0f * elam;
        float pc2  = 0.01f   * (1.0f / 12.0f) * 100.0f * efee * elam;
        g_stepc[tid] = make_float4(dm, fc, pc1, pc2);
    }

    // h1 for this block's 64 grid points; thread fills 32 k's for 2 g's
    {
        float s0 = (float)(gb * 64 + gl)      * H_S;
        float s1 = (float)(gb * 64 + gl + 32) * H_S;
        int   k0 = jc * 32;
#pragma unroll
        for (int k = 0; k < 32; ++k) {
            int kk = k0 + k;
            float wa = __ldg(W1 + kk);
            float wb = fmaf(tval, __ldg(W1 + HID + kk), __ldg(b1 + kk));
            h1s[gl     ][kk] = fmaxf(fmaf(s0, wa, wb), 0.0f);
            h1s[gl + 32][kk] = fmaxf(fmaf(s1, wa, wb), 0.0f);
        }
    }
    __syncthreads();

    // layer 2: 32 j-outputs (16 f32x2 pairs) for each of 2 grid points
    int j0 = jc * 32;
    u64 acc0[16], acc1[16];
#pragma unroll
    for (int q = 0; q < 8; ++q) {
        double2 b = __ldg((const double2*)(b2 + j0) + q);
        acc0[2*q  ] = acc1[2*q  ] = __double_as_longlong(b.x);
        acc0[2*q+1] = acc1[2*q+1] = __double_as_longlong(b.y);
    }
#pragma unroll 4
    for (int k = 0; k < HID; ++k) {
        u64 ha2 = pack2(h1s[gl     ][k], h1s[gl     ][k]);
        u64 hb2 = pack2(h1s[gl + 32][k], h1s[gl + 32][k]);
        const double2* wrow = (const double2*)(W2 + k * HID + j0);
#pragma unroll
        for (int q = 0; q < 8; ++q) {
            double2 w = __ldg(wrow + q);          // 4 floats = 2 f32x2 operands
            u64 w0 = __double_as_longlong(w.x);
            u64 w1 = __double_as_longlong(w.y);
            acc0[2*q  ] = fma2(ha2, w0, acc0[2*q  ]);
            acc0[2*q+1] = fma2(ha2, w1, acc0[2*q+1]);
            acc1[2*q  ] = fma2(hb2, w0, acc1[2*q  ]);
            acc1[2*q+1] = fma2(hb2, w1, acc1[2*q+1]);
        }
    }

    // layer 3 partial dot (unpack, relu, dot with W3)
    float oa = 0.0f, ob = 0.0f;
#pragma unroll
    for (int q = 0; q < 16; ++q) {
        float2 w3 = __ldg((const float2*)(W3 + j0) + q);
        float x0, x1, y0, y1;
        unpack2(acc0[q], x0, x1);
        unpack2(acc1[q], y0, y1);
        oa = fmaf(fmaxf(x0, 0.0f), w3.x, oa);
        oa = fmaf(fmaxf(x1, 0.0f), w3.y, oa);
        ob = fmaf(fmaxf(y0, 0.0f), w3.x, ob);
        ob = fmaf(fmaxf(y1, 0.0f), w3.y, ob);
    }
    part[jc][gl]      = oa;
    part[jc][gl + 32] = ob;
    __syncthreads();

    if (tid < 64) {
        float o = __ldg(b3) + part[0][tid] + part[1][tid] + part[2][tid] + part[3][tid];
        g_table[step * GP + gb * 64 + tid] = o;
    }
}

// ---------------------------------------------------------------------------
// Phase 2: per-path PnL. Steps are independent terms -> 6 chunks of 10 per
// path (12288 warps), smem reduce. Block = 64 paths x 6 chunks.
// ---------------------------------------------------------------------------
__global__ __launch_bounds__(384)
void va_path_kernel(const float* __restrict__ spots, float* __restrict__ out)
{
    __shared__ float red[6][64];

    int tid   = threadIdx.x;
    int chunk = tid >> 6;              // 0..5
    int pl    = tid & 63;
    int p     = blockIdx.x * 64 + pl;
    int i0    = chunk * 10;

    float pnl = 0.0f;
    float s = __ldg(spots + i0 * NBATCH + p);

#pragma unroll
    for (int k = 0; k < 10; ++k) {
        int i = i0 + k;
        float s_next = __ldg(spots + (i + 1) * NBATCH + p);
        float4 c = __ldg(&g_stepc[i]);

        // exact-PWL lerp on linear spot grid (s >= 0 always; clamp high only)
        float u = fminf(s * INV_HS, 190.999f);
        int   ig = (int)u;
        float f  = u - (float)ig;
        const float* row = g_table + i * GP + ig;
        float o0 = __ldg(row);
        float o1 = __ldg(row + 1);
        float netv = fmaf(o1 - o0, f, o0);

        // delta = -(net^2) * dm   (min(exp(-0.01*delta),1) == 1 exactly)
        float delta = -(netv * netv) * c.x;
        // inc_pnl = fee - payout = fc*s - max(pc1 - pc2*s, 0)
        float inc = fmaf(c.y, s, -fmaxf(fmaf(-c.w, s, c.z), 0.0f));

        pnl = pnl + inc + delta * (s_next - s);
        s = s_next;
    }

    red[chunk][pl] = pnl;
    __syncthreads();

    if (tid < 64) {
        out[blockIdx.x * 64 + tid] =
            ((red[0][tid] + red[1][tid]) + (red[2][tid] + red[3][tid]))
            + (red[4][tid] + red[5][tid]);
    }
}

// ---------------------------------------------------------------------------
extern "C" void kernel_launch(void* const* d_in, const int* in_sizes, int n_in,
                              void* d_out, int out_size)
{
    const float* spots = (const float*)d_in[0];   // [61, 65536]
    const float* W1    = (const float*)d_in[1];   // [2, 128]
    const float* b1    = (const float*)d_in[2];   // [128]
    const float* W2    = (const float*)d_in[3];   // [128, 128]
    const float* b2    = (const float*)d_in[4];   // [128]
    const float* W3    = (const float*)d_in[5];   // [128, 1]
    const float* b3    = (const float*)d_in[6];   // [1]

    va_table_kernel<<<NSTEP * 3, 128>>>(W1, b1, W2, b2, W3, b3);
    va_path_kernel<<<NBATCH / 64, 384>>>(spots, (float*)d_out);
}